// round 1
// baseline (speedup 1.0000x reference)
#include <cuda_runtime.h>
#include <cstddef>

// Problem constants
#define BB 8
#define LL 256
#define HH 128
#define NHH 4
#define RR (BB*LL)          // 2048 rows
#define EPSV 1e-8f
#define NEGV (-4294967295.0f)
#define SCALEV 0.17677669529663687f   // 1/sqrt(32)

// Scratch (device globals: no allocation allowed)
__device__ float g_q[RR*HH];            // ln1 output (residual source)
__device__ float g_Qb[RR*HH];
__device__ float g_Kb[RR*HH];
__device__ float g_Vb[RR*HH];
__device__ float g_qa1[RR*NHH*HH];      // 4 MB
__device__ float g_y[RR*HH];            // ln2 output
__device__ float g_h[RR*HH];            // ffn hidden
__device__ float g_x[RR*HH];            // running x between blocks

__device__ __forceinline__ float dot4(float4 a, float4 b) {
    return fmaf(a.x,b.x, fmaf(a.y,b.y, fmaf(a.z,b.z, a.w*b.w)));
}
__device__ __forceinline__ void fma4(float4& a, float s, float4 b) {
    a.x = fmaf(s,b.x,a.x); a.y = fmaf(s,b.y,a.y);
    a.z = fmaf(s,b.z,a.z); a.w = fmaf(s,b.w,a.w);
}

// -------------------- LayerNorm: one row per block, 128 threads -----------
__global__ void ln_kernel(const float* __restrict__ in, float* __restrict__ out,
                          const float* __restrict__ gw, const float* __restrict__ gb)
{
    __shared__ float red[4];
    int row = blockIdx.x;
    int t = threadIdx.x;
    float x = in[row*HH + t];
    float s = x;
    #pragma unroll
    for (int o = 16; o; o >>= 1) s += __shfl_xor_sync(0xffffffffu, s, o);
    if ((t & 31) == 0) red[t >> 5] = s;
    __syncthreads();
    float mean = (red[0]+red[1]+red[2]+red[3]) * (1.0f/HH);
    __syncthreads();
    float d = x - mean;
    float sq = d * d;
    #pragma unroll
    for (int o = 16; o; o >>= 1) sq += __shfl_xor_sync(0xffffffffu, sq, o);
    if ((t & 31) == 0) red[t >> 5] = sq;
    __syncthreads();
    float var = (red[0]+red[1]+red[2]+red[3]) * (1.0f/HH);
    out[row*HH + t] = d * rsqrtf(var + EPSV) * gw[t] + gb[t];
}

// -------------------- GEMM: out[2048,128] = A[2048,128] @ W[128,128]^T ----
// BM=16 rows/block (128 blocks), 256 threads, each thread: 2 rows x 4 cols.
__global__ void gemm_kernel(const float* __restrict__ A, const float* __restrict__ W,
                            const float* __restrict__ bias, float* __restrict__ out,
                            const float* __restrict__ resid,
                            const unsigned char* __restrict__ keep, int relu)
{
    __shared__ float sA[16][33];
    __shared__ float sW[32][128];
    int tid = threadIdx.x;
    int tx = tid & 31, ty = tid >> 5;
    int row0 = blockIdx.x * 16;

    float4 acc0 = make_float4(0,0,0,0);
    float4 acc1 = make_float4(0,0,0,0);

    for (int k0 = 0; k0 < 128; k0 += 32) {
        if (tid < 128) {
            int r = tid >> 3, c4 = (tid & 7) * 4;
            float4 v = __ldg(reinterpret_cast<const float4*>(A + (size_t)(row0+r)*HH + k0 + c4));
            sA[r][c4] = v.x; sA[r][c4+1] = v.y; sA[r][c4+2] = v.z; sA[r][c4+3] = v.w;
        }
        #pragma unroll
        for (int q = 0; q < 4; q++) {
            int fi = tid + 256*q;
            int col = fi >> 3, kq = (fi & 7) * 4;
            float4 v = __ldg(reinterpret_cast<const float4*>(W + (size_t)col*HH + k0 + kq));
            sW[kq][col] = v.x; sW[kq+1][col] = v.y; sW[kq+2][col] = v.z; sW[kq+3][col] = v.w;
        }
        __syncthreads();
        #pragma unroll
        for (int kk = 0; kk < 32; kk++) {
            float4 w4 = *reinterpret_cast<const float4*>(&sW[kk][tx*4]);
            float a0 = sA[ty*2][kk];
            float a1 = sA[ty*2+1][kk];
            fma4(acc0, a0, w4);
            fma4(acc1, a1, w4);
        }
        __syncthreads();
    }

    float4 bb = __ldg(reinterpret_cast<const float4*>(bias + tx*4));
    #pragma unroll
    for (int rr = 0; rr < 2; rr++) {
        float4 o = (rr == 0) ? acc0 : acc1;
        o.x += bb.x; o.y += bb.y; o.z += bb.z; o.w += bb.w;
        if (relu) {
            o.x = fmaxf(o.x, 0.f); o.y = fmaxf(o.y, 0.f);
            o.z = fmaxf(o.z, 0.f); o.w = fmaxf(o.w, 0.f);
        }
        int row = row0 + ty*2 + rr;
        if (resid) {
            float4 rv = __ldg(reinterpret_cast<const float4*>(resid + (size_t)row*HH + tx*4));
            o.x += rv.x; o.y += rv.y; o.z += rv.z; o.w += rv.w;
        }
        if (keep && keep[row]) { o.x = 0.f; o.y = 0.f; o.z = 0.f; o.w = 0.f; }
        *reinterpret_cast<float4*>(out + (size_t)row*HH + tx*4) = o;
    }
}

// -------------------- qa1[row,h,e] = sum_d Q[row,32h+d]*WA1[32h+d,e] ------
__global__ void qa1_kernel(const float* __restrict__ Q, const float* __restrict__ WA1,
                           float* __restrict__ qa1)
{
    __shared__ float sQ[HH];
    int row = blockIdx.x;
    int t = threadIdx.x;          // 128 threads
    sQ[t] = Q[(size_t)row*HH + t];
    __syncthreads();
    int g = t >> 5;               // head = row-group of WA1
    int e4 = t & 31;
    float4 acc = make_float4(0,0,0,0);
    const float4* Wp = reinterpret_cast<const float4*>(WA1);
    #pragma unroll
    for (int cc = 0; cc < 32; cc++) {
        int c = g*32 + cc;
        float4 w = __ldg(&Wp[(size_t)c*32 + e4]);
        fma4(acc, sQ[c], w);
    }
    reinterpret_cast<float4*>(qa1)[((size_t)row*NHH + g)*32 + e4] = acc;
}

// -------------------- Fused attention: one CTA per (b,i) row --------------
// Pass1: scores[h,j] = (Qh.Kh[j] + tm[b,i,j,:].qa1[h,:])/sqrt(d), masked
// Softmax per head; Pass2: out_h += w.Vh, tws[h,:] += w * tm row
// Epilogue: out_h += tws[h] @ WA2_h^T ; residual add (g_q); fused LN2 -> y
__global__ void attn_kernel(
    const float* __restrict__ tm, const unsigned char* __restrict__ tmask,
    const float* __restrict__ Qm, const float* __restrict__ Km,
    const float* __restrict__ Vm, const float* __restrict__ qa1,
    const float* __restrict__ qres, const float* __restrict__ WA2,
    const float* __restrict__ ln2g, const float* __restrict__ ln2b,
    float* __restrict__ yout)
{
    __shared__ float sQ[HH];
    __shared__ float sQA[NHH][HH];
    __shared__ float sS[NHH][LL];
    __shared__ float sPT[8][NHH][HH];
    __shared__ float sPV[8][HH];
    __shared__ float sT[NHH][HH];
    __shared__ float sX[HH];
    __shared__ float sred[2];

    int row = blockIdx.x;
    int b = row >> 8;
    int i = row & 255;
    int tid = threadIdx.x;
    int w = tid >> 5, lane = tid & 31;

    if (tid < HH) sQ[tid] = Qm[(size_t)row*HH + tid];
    {
        const float* qa = qa1 + (size_t)row * NHH * HH;
        (&sQA[0][0])[tid]       = qa[tid];
        (&sQA[0][0])[tid + 256] = qa[tid + 256];
    }
    __syncthreads();

    const bool rowmask = tmask[row] != 0;
    const float4* tmr = reinterpret_cast<const float4*>(tm + (size_t)row * LL * HH);
    const float4* K4  = reinterpret_cast<const float4*>(Km + (size_t)b * LL * HH);
    const float4* V4  = reinterpret_cast<const float4*>(Vm + (size_t)b * LL * HH);

    float4 a0 = *reinterpret_cast<const float4*>(&sQA[0][lane*4]);
    float4 a1 = *reinterpret_cast<const float4*>(&sQA[1][lane*4]);
    float4 a2 = *reinterpret_cast<const float4*>(&sQA[2][lane*4]);
    float4 a3 = *reinterpret_cast<const float4*>(&sQA[3][lane*4]);
    float4 q4 = *reinterpret_cast<const float4*>(&sQ[lane*4]);
    int hq = lane >> 3;
    int j0 = w * 32;

    // ---- pass 1: scores ----
    #pragma unroll 4
    for (int jj = 0; jj < 32; jj++) {
        int j = j0 + jj;
        float4 t4 = __ldg(&tmr[(size_t)j*32 + lane]);
        float4 k4 = __ldg(&K4[(size_t)j*32 + lane]);
        float p0 = dot4(t4, a0);
        float p1 = dot4(t4, a1);
        float p2 = dot4(t4, a2);
        float p3 = dot4(t4, a3);
        float qk = dot4(q4, k4);
        p0 += (hq == 0) ? qk : 0.f;
        p1 += (hq == 1) ? qk : 0.f;
        p2 += (hq == 2) ? qk : 0.f;
        p3 += (hq == 3) ? qk : 0.f;
        #pragma unroll
        for (int o = 16; o; o >>= 1) {
            p0 += __shfl_xor_sync(0xffffffffu, p0, o);
            p1 += __shfl_xor_sync(0xffffffffu, p1, o);
            p2 += __shfl_xor_sync(0xffffffffu, p2, o);
            p3 += __shfl_xor_sync(0xffffffffu, p3, o);
        }
        if (lane < 4) {
            float pv = (lane == 0) ? p0 : (lane == 1) ? p1 : (lane == 2) ? p2 : p3;
            bool m = rowmask || (j > i);
            sS[lane][j] = m ? NEGV : pv * SCALEV;
        }
    }
    __syncthreads();

    // ---- softmax: warp h handles head h ----
    if (w < 4) {
        float vals[8];
        float mx = -3.4e38f;
        #pragma unroll
        for (int k = 0; k < 8; k++) { vals[k] = sS[w][lane + 32*k]; mx = fmaxf(mx, vals[k]); }
        #pragma unroll
        for (int o = 16; o; o >>= 1) mx = fmaxf(mx, __shfl_xor_sync(0xffffffffu, mx, o));
        float sm = 0.f;
        #pragma unroll
        for (int k = 0; k < 8; k++) { vals[k] = expf(vals[k] - mx); sm += vals[k]; }
        #pragma unroll
        for (int o = 16; o; o >>= 1) sm += __shfl_xor_sync(0xffffffffu, sm, o);
        float inv = 1.0f / sm;
        #pragma unroll
        for (int k = 0; k < 8; k++) sS[w][lane + 32*k] = vals[k] * inv;
    }
    __syncthreads();

    // ---- pass 2: weighted V and weighted tm sums ----
    float4 av = make_float4(0,0,0,0);
    float4 t0 = make_float4(0,0,0,0), t1 = t0, t2 = t0, t3 = t0;
    #pragma unroll 4
    for (int jj = 0; jj < 32; jj++) {
        int j = j0 + jj;
        float4 tv = __ldg(&tmr[(size_t)j*32 + lane]);
        float4 vv = __ldg(&V4[(size_t)j*32 + lane]);
        float w0 = sS[0][j], w1 = sS[1][j], w2 = sS[2][j], w3 = sS[3][j];
        float wq = (hq == 0) ? w0 : (hq == 1) ? w1 : (hq == 2) ? w2 : w3;
        fma4(av, wq, vv);
        fma4(t0, w0, tv); fma4(t1, w1, tv); fma4(t2, w2, tv); fma4(t3, w3, tv);
    }
    *reinterpret_cast<float4*>(&sPT[w][0][lane*4]) = t0;
    *reinterpret_cast<float4*>(&sPT[w][1][lane*4]) = t1;
    *reinterpret_cast<float4*>(&sPT[w][2][lane*4]) = t2;
    *reinterpret_cast<float4*>(&sPT[w][3][lane*4]) = t3;
    *reinterpret_cast<float4*>(&sPV[w][lane*4]) = av;
    __syncthreads();

    // ---- reduce warp partials ----
    #pragma unroll
    for (int f = tid; f < NHH*HH; f += 256) {
        int h = f >> 7, e = f & 127;
        float s = 0.f;
        #pragma unroll
        for (int ww = 0; ww < 8; ww++) s += sPT[ww][h][e];
        sT[h][e] = s;
    }
    float vsum = 0.f;
    if (tid < HH) {
        #pragma unroll
        for (int ww = 0; ww < 8; ww++) vsum += sPV[ww][tid];
    }
    __syncthreads();

    // ---- epilogue: WA2 term + residual ----
    if (tid < HH) {
        int h = tid >> 5;
        const float4* wr = reinterpret_cast<const float4*>(WA2 + (size_t)tid*HH);
        const float4* tr = reinterpret_cast<const float4*>(&sT[h][0]);
        float acc = 0.f;
        #pragma unroll
        for (int k = 0; k < 32; k++) acc += dot4(__ldg(&wr[k]), tr[k]);
        float xv = qres[(size_t)row*HH + tid] + vsum + acc;
        sX[tid] = xv;
    }
    __syncthreads();

    // ---- fused LN2 ----
    if (tid < 32) {
        float s = sX[lane] + sX[lane+32] + sX[lane+64] + sX[lane+96];
        #pragma unroll
        for (int o = 16; o; o >>= 1) s += __shfl_xor_sync(0xffffffffu, s, o);
        if (lane == 0) sred[0] = s * (1.0f/HH);
    }
    __syncthreads();
    float mn = sred[0];
    if (tid < 32) {
        float d0 = sX[lane]      - mn;
        float d1 = sX[lane + 32] - mn;
        float d2 = sX[lane + 64] - mn;
        float d3 = sX[lane + 96] - mn;
        float s = d0*d0 + d1*d1 + d2*d2 + d3*d3;
        #pragma unroll
        for (int o = 16; o; o >>= 1) s += __shfl_xor_sync(0xffffffffu, s, o);
        if (lane == 0) sred[1] = s * (1.0f/HH);
    }
    __syncthreads();
    if (tid < HH) {
        float iv = rsqrtf(sred[1] + EPSV);
        yout[(size_t)row*HH + tid] = (sX[tid] - mn) * iv * ln2g[tid] + ln2b[tid];
    }
}

// ==========================================================================
extern "C" void kernel_launch(void* const* d_in, const int* in_sizes, int n_in,
                              void* d_out, int out_size)
{
    const float* seqs = (const float*)d_in[0];
    const unsigned char* tmask = (const unsigned char*)d_in[1];
    const float* tm   = (const float*)d_in[2];
    const float* Qw   = (const float*)d_in[3];
    const float* Qbp  = (const float*)d_in[4];
    const float* Kw   = (const float*)d_in[5];
    const float* Kbp  = (const float*)d_in[6];
    const float* Vw   = (const float*)d_in[7];
    const float* Vbp  = (const float*)d_in[8];
    const float* WA1  = (const float*)d_in[9];
    const float* WA2  = (const float*)d_in[10];
    const float* ln1g = (const float*)d_in[11];
    const float* ln1b = (const float*)d_in[12];
    const float* ln2g = (const float*)d_in[13];
    const float* ln2b = (const float*)d_in[14];
    const float* c1w  = (const float*)d_in[15];
    const float* c1b  = (const float*)d_in[16];
    const float* c2w  = (const float*)d_in[17];
    const float* c2b  = (const float*)d_in[18];
    const float* lnfg = (const float*)d_in[19];
    const float* lnfb = (const float*)d_in[20];
    float* out = (float*)d_out;

    float *pq, *pQ, *pK, *pV, *pqa, *py, *ph, *px;
    cudaGetSymbolAddress((void**)&pq,  g_q);
    cudaGetSymbolAddress((void**)&pQ,  g_Qb);
    cudaGetSymbolAddress((void**)&pK,  g_Kb);
    cudaGetSymbolAddress((void**)&pV,  g_Vb);
    cudaGetSymbolAddress((void**)&pqa, g_qa1);
    cudaGetSymbolAddress((void**)&py,  g_y);
    cudaGetSymbolAddress((void**)&ph,  g_h);
    cudaGetSymbolAddress((void**)&px,  g_x);

    const int HW = HH * HH;
    for (int blk = 0; blk < 2; blk++) {
        const float* xin = (blk == 0) ? seqs : px;
        ln_kernel<<<RR, 128>>>(xin, pq, ln1g + blk*HH, ln1b + blk*HH);
        gemm_kernel<<<RR/16, 256>>>(pq, Qw + blk*HW, Qbp + blk*HH, pQ, nullptr, nullptr, 0);
        gemm_kernel<<<RR/16, 256>>>(pq, Kw + blk*HW, Kbp + blk*HH, pK, nullptr, nullptr, 0);
        gemm_kernel<<<RR/16, 256>>>(pq, Vw + blk*HW, Vbp + blk*HH, pV, nullptr, nullptr, 0);
        qa1_kernel<<<RR, 128>>>(pQ, WA1 + blk*HW, pqa);
        attn_kernel<<<RR, 256>>>(tm, tmask, pQ, pK, pV, pqa, pq,
                                 WA2 + blk*HW, ln2g + blk*HH, ln2b + blk*HH, py);
        gemm_kernel<<<RR/16, 256>>>(py, c1w + blk*HW, c1b + blk*HH, ph, nullptr, nullptr, 1);
        gemm_kernel<<<RR/16, 256>>>(ph, c2w + blk*HW, c2b + blk*HH, px, py, tmask, 0);
    }
    ln_kernel<<<RR, 128>>>(px, out, lnfg, lnfb);
}